// round 2
// baseline (speedup 1.0000x reference)
#include <cuda_runtime.h>
#include <math.h>

#define IMG 40
#define HW 1600   // 40*40
#define BATCH 256
#define CH 40

// Ping-pong scratch: [256, 40, 1600] complex = 131 MB each. Static device
// arrays (no allocation anywhere, per harness rules). Accessed ONLY from
// device code (no cudaGetSymbolAddress needed).
__device__ float2 g_bufA[(size_t)BATCH * CH * HW];
__device__ float2 g_bufB[(size_t)BATCH * CH * HW];
__device__ float2 g_D[HW];   // forward DFT matrix (ortho norm per 1D pass)

template <int B>
__device__ __forceinline__ float2* getbuf() {
    return (B == 0) ? g_bufA : g_bufB;
}

// ---------------------------------------------------------------------------
// init: D[k*40+n] = exp(-i*2*pi*k*n/40) / sqrt(40). k*n reduced mod 40 for
// exact angles. Inverse transform uses conj(D) (template flag, free negates).
// ---------------------------------------------------------------------------
__global__ void init_D_kernel() {
    int idx = blockIdx.x * blockDim.x + threadIdx.x;
    if (idx >= HW) return;
    int k = idx / IMG, n = idx % IMG;
    int m = (k * n) % IMG;
    float theta = 2.0f * 3.14159265358979323846f * (float)m / (float)IMG;
    float s, c;
    sincosf(theta, &s, &c);
    float nrm = rsqrtf((float)IMG);
    g_D[idx] = make_float2(c * nrm, -s * nrm);
}

__device__ __forceinline__ void cmac(float2& a, float2 z, float2 d) {
    a.x = fmaf(z.x, d.x, a.x);
    a.x = fmaf(-z.y, d.y, a.x);
    a.y = fmaf(z.x, d.y, a.y);
    a.y = fmaf(z.y, d.x, a.y);
}

// a += z * d  (CONJ=false)   |   a += z * conj(d)  (CONJ=true)
template <bool CONJ>
__device__ __forceinline__ void cmacD(float2& a, float2 z, float2 d) {
    if (CONJ) d.y = -d.y;   // compile-time: folds into FFMA negate modifiers
    cmac(a, z, d);
}

// ---------------------------------------------------------------------------
// Core: 2D 40x40 DFT of the smem image Z into registers, two matmul passes.
// Thread t: column k = t%40, row group g = t/40 (rows g, g+10, g+20, g+30).
// Caller must __syncthreads() after filling Z. No trailing sync.
// ---------------------------------------------------------------------------
template <bool CONJ>
__device__ __forceinline__ void dft2d(
    const float2 (*Z)[IMG], float2 (*T)[IMG + 1], const float2 (*Ds)[IMG + 1],
    int k, int g, float2& a0, float2& a1, float2& a2, float2& a3)
{
    a0 = a1 = a2 = a3 = make_float2(0.f, 0.f);
    // Pass 1 (row transform): T[h][k] = sum_w Z[h][w] * D(k,w)
    #pragma unroll 8
    for (int w = 0; w < IMG; w++) {
        float2 d = Ds[w][k];
        cmacD<CONJ>(a0, Z[g][w], d);
        cmacD<CONJ>(a1, Z[g + 10][w], d);
        cmacD<CONJ>(a2, Z[g + 20][w], d);
        cmacD<CONJ>(a3, Z[g + 30][w], d);
    }
    T[g][k] = a0;
    T[g + 10][k] = a1;
    T[g + 20][k] = a2;
    T[g + 30][k] = a3;
    __syncthreads();
    // Pass 2 (col transform): out[r][k] = sum_h T[h][k] * D(r,h)
    a0 = a1 = a2 = a3 = make_float2(0.f, 0.f);
    #pragma unroll 8
    for (int h = 0; h < IMG; h++) {
        float2 tv = T[h][k];
        cmacD<CONJ>(a0, tv, Ds[h][g]);
        cmacD<CONJ>(a1, tv, Ds[h][g + 10]);
        cmacD<CONJ>(a2, tv, Ds[h][g + 20]);
        cmacD<CONJ>(a3, tv, Ds[h][g + 30]);
    }
}

__device__ __forceinline__ void load_D_smem(float2 (*Ds)[IMG + 1], int t) {
    #pragma unroll
    for (int r = 0; r < 4; r++) {
        int idx = t + 400 * r;
        Ds[idx / IMG][idx % IMG] = g_D[idx];
    }
}

// ---------------------------------------------------------------------------
// First kernel: forward FFT of the real input x -> freq in DST buffer.
// ---------------------------------------------------------------------------
template <int DST>
__global__ __launch_bounds__(400) void fft_first_kernel(const float* __restrict__ x)
{
    __shared__ float2 Z[IMG][IMG];
    __shared__ float2 T[IMG][IMG + 1];
    __shared__ float2 Ds[IMG][IMG + 1];

    const int t = threadIdx.x;
    const size_t img = blockIdx.x;
    load_D_smem(Ds, t);
    const float* in = x + img * HW;
    #pragma unroll
    for (int r = 0; r < 4; r++) {
        int idx = t + 400 * r;
        Z[idx / IMG][idx % IMG] = make_float2(in[idx], 0.0f);
    }
    __syncthreads();

    const int k = t % IMG, g = t / IMG;
    float2 a0, a1, a2, a3;
    dft2d<false>(Z, T, Ds, k, g, a0, a1, a2, a3);

    float2* out = getbuf<DST>() + img * HW;
    out[(g)      * IMG + k] = a0;
    out[(g + 10) * IMG + k] = a1;
    out[(g + 20) * IMG + k] = a2;
    out[(g + 30) * IMG + k] = a3;
}

// ---------------------------------------------------------------------------
// Fused layer boundary: freq SRC -> ifft -> CReLU -> fft -> freq DST.
// Four 40x40 matmul passes, all in SMEM; one global read + one write.
// ---------------------------------------------------------------------------
template <int SRC, int DST>
__global__ __launch_bounds__(400) void fused_ifft_crelu_fft_kernel()
{
    __shared__ float2 Z[IMG][IMG];
    __shared__ float2 T[IMG][IMG + 1];
    __shared__ float2 Ds[IMG][IMG + 1];

    const int t = threadIdx.x;
    const size_t img = blockIdx.x;
    load_D_smem(Ds, t);
    const float2* in = getbuf<SRC>() + img * HW;
    #pragma unroll
    for (int r = 0; r < 4; r++) {
        int idx = t + 400 * r;
        Z[idx / IMG][idx % IMG] = in[idx];
    }
    __syncthreads();

    const int k = t % IMG, g = t / IMG;
    float2 a0, a1, a2, a3;
    dft2d<true>(Z, T, Ds, k, g, a0, a1, a2, a3);  // inverse FFT (ortho)

    // CReLU, store back into Z (spatial domain)
    a0.x = fmaxf(a0.x, 0.f); a0.y = fmaxf(a0.y, 0.f);
    a1.x = fmaxf(a1.x, 0.f); a1.y = fmaxf(a1.y, 0.f);
    a2.x = fmaxf(a2.x, 0.f); a2.y = fmaxf(a2.y, 0.f);
    a3.x = fmaxf(a3.x, 0.f); a3.y = fmaxf(a3.y, 0.f);
    Z[g][k] = a0;
    Z[g + 10][k] = a1;
    Z[g + 20][k] = a2;
    Z[g + 30][k] = a3;
    __syncthreads();

    dft2d<false>(Z, T, Ds, k, g, a0, a1, a2, a3);  // forward FFT

    float2* out = getbuf<DST>() + img * HW;
    out[(g)      * IMG + k] = a0;
    out[(g + 10) * IMG + k] = a1;
    out[(g + 20) * IMG + k] = a2;
    out[(g + 30) * IMG + k] = a3;
}

// ---------------------------------------------------------------------------
// Last kernel: inverse FFT, write real part to harness output.
// ---------------------------------------------------------------------------
template <int SRC>
__global__ __launch_bounds__(400) void ifft_last_kernel(float* __restrict__ outp)
{
    __shared__ float2 Z[IMG][IMG];
    __shared__ float2 T[IMG][IMG + 1];
    __shared__ float2 Ds[IMG][IMG + 1];

    const int t = threadIdx.x;
    const size_t img = blockIdx.x;
    load_D_smem(Ds, t);
    const float2* in = getbuf<SRC>() + img * HW;
    #pragma unroll
    for (int r = 0; r < 4; r++) {
        int idx = t + 400 * r;
        Z[idx / IMG][idx % IMG] = in[idx];
    }
    __syncthreads();

    const int k = t % IMG, g = t / IMG;
    float2 a0, a1, a2, a3;
    dft2d<true>(Z, T, Ds, k, g, a0, a1, a2, a3);

    float* out = outp + img * HW;
    out[(g)      * IMG + k] = a0.x;
    out[(g + 10) * IMG + k] = a1.x;
    out[(g + 20) * IMG + k] = a2.x;
    out[(g + 30) * IMG + k] = a3.x;
}

// ---------------------------------------------------------------------------
// Middle-layer channel mix (inC = outC = 40):
//   O[b,o,hw] = sum_i F[b,i,hw] * W[i,o,hw]
// One block per (frequency bin, batch-tile of 16). W bin tile cached in SMEM.
// ---------------------------------------------------------------------------
template <int SRC, int DST>
__global__ __launch_bounds__(640) void mix40_kernel(const float2* __restrict__ W)
{
    __shared__ float2 Ws[CH][CH];   // [i][o]
    __shared__ float2 Fs[16][CH];   // [bl][i]

    const float2* F = getbuf<SRC>();
    float2* O = getbuf<DST>();

    const int hw = blockIdx.x;
    const int b0 = blockIdx.y * 16;
    const int o  = threadIdx.x;   // 0..39
    const int bl = threadIdx.y;   // 0..15
    const int tid = bl * CH + o;

    for (int idx = tid; idx < CH * CH; idx += 640) {
        Ws[idx / CH][idx % CH] = W[(size_t)idx * HW + hw];
    }
    Fs[bl][o] = F[((size_t)(b0 + bl) * CH + o) * HW + hw];
    __syncthreads();

    float2 acc = {0, 0};
    #pragma unroll
    for (int i = 0; i < CH; i++) {
        cmac(acc, Fs[bl][i], Ws[i][o]);
    }
    O[((size_t)(b0 + bl) * CH + o) * HW + hw] = acc;
}

// Layer-1 mix (inC = 1): O[b,o,hw] = F[b,0,hw] * W[0,o,hw]  (elementwise)
template <int SRC, int DST>
__global__ void mix1_kernel(const float2* __restrict__ W)
{
    const float2* F = getbuf<SRC>();
    float2* O = getbuf<DST>();
    int idx = blockIdx.x * blockDim.x + threadIdx.x;  // 256*40*1600 total
    int b   = idx / (CH * HW);
    int rem = idx % (CH * HW);
    int hw  = rem % HW;
    float2 f = F[(size_t)b * HW + hw];
    float2 w = W[rem];  // (o*HW + hw)
    float2 acc = {0, 0};
    cmac(acc, f, w);
    O[idx] = acc;
}

// Layer-6 mix (outC = 1): O[b,hw] = sum_i F[b,i,hw] * W[i,0,hw]
template <int SRC, int DST>
__global__ __launch_bounds__(400) void mix6_kernel(const float2* __restrict__ W)
{
    const float2* F = getbuf<SRC>();
    float2* O = getbuf<DST>();
    const int b = blockIdx.x;
    #pragma unroll
    for (int r = 0; r < 4; r++) {
        int hw = threadIdx.x + 400 * r;
        float2 acc = {0, 0};
        #pragma unroll 8
        for (int i = 0; i < CH; i++) {
            cmac(acc, F[((size_t)b * CH + i) * HW + hw], W[(size_t)i * HW + hw]);
        }
        O[(size_t)b * HW + hw] = acc;
    }
}

extern "C" void kernel_launch(void* const* d_in, const int* in_sizes, int n_in,
                              void* d_out, int out_size)
{
    const float*  x  = (const float*)d_in[0];
    const float2* w1 = (const float2*)d_in[1];
    const float2* w2 = (const float2*)d_in[2];
    const float2* w3 = (const float2*)d_in[3];
    const float2* w4 = (const float2*)d_in[4];
    const float2* w5 = (const float2*)d_in[5];
    const float2* w6 = (const float2*)d_in[6];
    float* out = (float*)d_out;

    const dim3 mixGrid(HW, BATCH / 16);
    const dim3 mixBlk(CH, 16);
    const int nImgAll = BATCH * CH;   // 10240

    init_D_kernel<<<4, 400>>>();

    // Layer 1 (inC=1 -> outC=40)
    fft_first_kernel<0><<<BATCH, 400>>>(x);                 // x -> A (freq)
    mix1_kernel<0, 1><<<(BATCH * CH * HW) / 256, 256>>>(w1); // A -> B
    fused_ifft_crelu_fft_kernel<1, 0><<<nImgAll, 400>>>();   // B -> A

    // Layer 2
    mix40_kernel<0, 1><<<mixGrid, mixBlk>>>(w2);             // A -> B
    fused_ifft_crelu_fft_kernel<1, 0><<<nImgAll, 400>>>();   // B -> A

    // Layer 3
    mix40_kernel<0, 1><<<mixGrid, mixBlk>>>(w3);
    fused_ifft_crelu_fft_kernel<1, 0><<<nImgAll, 400>>>();

    // Layer 4
    mix40_kernel<0, 1><<<mixGrid, mixBlk>>>(w4);
    fused_ifft_crelu_fft_kernel<1, 0><<<nImgAll, 400>>>();

    // Layer 5
    mix40_kernel<0, 1><<<mixGrid, mixBlk>>>(w5);
    fused_ifft_crelu_fft_kernel<1, 0><<<nImgAll, 400>>>();   // B -> A (freq in of L6)

    // Layer 6 (inC=40 -> outC=1), final output = real(ifft2)
    mix6_kernel<0, 1><<<BATCH, 400>>>(w6);                   // A -> B ([256,1600])
    ifft_last_kernel<1><<<BATCH, 400>>>(out);                // B -> out (real)
}

// round 3
// speedup vs baseline: 1.3875x; 1.3875x over previous
#include <cuda_runtime.h>
#include <math.h>

#define IMG 40
#define HW 1600
#define BATCH 256
#define CH 40

// Ping-pong scratch (131 MB each), device-side only.
__device__ float2 g_bufA[(size_t)BATCH * CH * HW];
__device__ float2 g_bufB[(size_t)BATCH * CH * HW];
__device__ float2 g_D[HW];   // forward DFT matrix (ortho norm per 1D pass)

template <int B>
__device__ __forceinline__ float2* getbuf() {
    return (B == 0) ? g_bufA : g_bufB;
}

__global__ void init_D_kernel() {
    int idx = blockIdx.x * blockDim.x + threadIdx.x;
    if (idx >= HW) return;
    int k = idx / IMG, n = idx % IMG;
    int m = (k * n) % IMG;
    float theta = 2.0f * 3.14159265358979323846f * (float)m / (float)IMG;
    float s, c;
    sincosf(theta, &s, &c);
    float nrm = rsqrtf((float)IMG);
    g_D[idx] = make_float2(c * nrm, -s * nrm);
}

__device__ __forceinline__ void cmac(float2& a, float2 z, float2 d) {
    a.x = fmaf(z.x, d.x, a.x);
    a.x = fmaf(-z.y, d.y, a.x);
    a.y = fmaf(z.x, d.y, a.y);
    a.y = fmaf(z.y, d.x, a.y);
}

template <bool CONJ>
__device__ __forceinline__ void cmacD(float2& a, float2 z, float2 d) {
    if (CONJ) d.y = -d.y;   // compile-time; folds into FFMA negate modifiers
    cmac(a, z, d);
}

// ---------------------------------------------------------------------------
// Pair-of-images 2D DFT core. ZT holds two images interleaved per float4:
// (img0.re, img0.im, img1.re, img1.im). Thread t: k0=t%20 (cols k0,k0+20),
// r0=t/20 (rows r0,r0+20). In-place: T overwrites ZT between passes.
// After return, a[img][ri][ci] holds output at (row r0+20*ri, col k0+20*ci).
// Caller must __syncthreads() after filling ZT. No trailing sync.
// ---------------------------------------------------------------------------
template <bool CONJ>
__device__ __forceinline__ void dft2d_pair(
    float4 (*ZT)[IMG + 1], const float2 (*Ds)[IMG + 1],
    int k0, int r0, float2 a[2][2][2])
{
    #pragma unroll
    for (int i = 0; i < 2; i++)
        #pragma unroll
        for (int r = 0; r < 2; r++)
            #pragma unroll
            for (int c = 0; c < 2; c++)
                a[i][r][c] = make_float2(0.f, 0.f);

    // Pass 1: T(r,k) = sum_w Z(r,w) * D(k,w)
    #pragma unroll 4
    for (int w = 0; w < IMG; w++) {
        float2 d0 = Ds[w][k0];
        float2 d1 = Ds[w][k0 + 20];
        float4 z0 = ZT[r0][w];
        float4 z1 = ZT[r0 + 20][w];
        float2 z00 = {z0.x, z0.y}, z01 = {z0.z, z0.w};
        float2 z10 = {z1.x, z1.y}, z11 = {z1.z, z1.w};
        cmacD<CONJ>(a[0][0][0], z00, d0); cmacD<CONJ>(a[0][0][1], z00, d1);
        cmacD<CONJ>(a[1][0][0], z01, d0); cmacD<CONJ>(a[1][0][1], z01, d1);
        cmacD<CONJ>(a[0][1][0], z10, d0); cmacD<CONJ>(a[0][1][1], z10, d1);
        cmacD<CONJ>(a[1][1][0], z11, d0); cmacD<CONJ>(a[1][1][1], z11, d1);
    }
    __syncthreads();   // all pass-1 reads done; safe to overwrite in place
    ZT[r0][k0]           = make_float4(a[0][0][0].x, a[0][0][0].y, a[1][0][0].x, a[1][0][0].y);
    ZT[r0][k0 + 20]      = make_float4(a[0][0][1].x, a[0][0][1].y, a[1][0][1].x, a[1][0][1].y);
    ZT[r0 + 20][k0]      = make_float4(a[0][1][0].x, a[0][1][0].y, a[1][1][0].x, a[1][1][0].y);
    ZT[r0 + 20][k0 + 20] = make_float4(a[0][1][1].x, a[0][1][1].y, a[1][1][1].x, a[1][1][1].y);
    __syncthreads();

    #pragma unroll
    for (int i = 0; i < 2; i++)
        #pragma unroll
        for (int r = 0; r < 2; r++)
            #pragma unroll
            for (int c = 0; c < 2; c++)
                a[i][r][c] = make_float2(0.f, 0.f);

    // Pass 2: out(r,k) = sum_h T(h,k) * D(r,h)
    #pragma unroll 4
    for (int h = 0; h < IMG; h++) {
        float4 t0 = ZT[h][k0];
        float4 t1 = ZT[h][k0 + 20];
        float2 d0 = Ds[h][r0];
        float2 d1 = Ds[h][r0 + 20];
        float2 t00 = {t0.x, t0.y}, t01 = {t0.z, t0.w};
        float2 t10 = {t1.x, t1.y}, t11 = {t1.z, t1.w};
        cmacD<CONJ>(a[0][0][0], t00, d0); cmacD<CONJ>(a[0][1][0], t00, d1);
        cmacD<CONJ>(a[1][0][0], t01, d0); cmacD<CONJ>(a[1][1][0], t01, d1);
        cmacD<CONJ>(a[0][0][1], t10, d0); cmacD<CONJ>(a[0][1][1], t10, d1);
        cmacD<CONJ>(a[1][0][1], t11, d0); cmacD<CONJ>(a[1][1][1], t11, d1);
    }
}

__device__ __forceinline__ void load_D_smem(float2 (*Ds)[IMG + 1], int t) {
    #pragma unroll
    for (int r = 0; r < 4; r++) {
        int idx = t + 400 * r;
        Ds[idx / IMG][idx % IMG] = g_D[idx];
    }
}

// ---------------------------------------------------------------------------
// First: forward FFT of real input x (2 images/block) -> freq in DST.
// ---------------------------------------------------------------------------
template <int DST>
__global__ __launch_bounds__(400, 2) void fft_first_kernel(const float* __restrict__ x)
{
    __shared__ float4 ZT[IMG][IMG + 1];
    __shared__ float2 Ds[IMG][IMG + 1];
    const int t = threadIdx.x;
    const size_t i0 = (size_t)blockIdx.x * 2;
    load_D_smem(Ds, t);
    const float* in0 = x + i0 * HW;
    const float* in1 = in0 + HW;
    #pragma unroll
    for (int r = 0; r < 4; r++) {
        int idx = t + 400 * r;
        ZT[idx / IMG][idx % IMG] = make_float4(in0[idx], 0.f, in1[idx], 0.f);
    }
    __syncthreads();
    const int k0 = t % 20, r0 = t / 20;
    float2 a[2][2][2];
    dft2d_pair<false>(ZT, Ds, k0, r0, a);
    float2* o0 = getbuf<DST>() + i0 * HW;
    float2* o1 = o0 + HW;
    #pragma unroll
    for (int ri = 0; ri < 2; ri++)
        #pragma unroll
        for (int ci = 0; ci < 2; ci++) {
            int p = (r0 + 20 * ri) * IMG + (k0 + 20 * ci);
            o0[p] = a[0][ri][ci];
            o1[p] = a[1][ri][ci];
        }
}

// ---------------------------------------------------------------------------
// Fused boundary: freq SRC -> ifft -> CReLU -> fft -> freq DST. 2 img/block.
// ---------------------------------------------------------------------------
template <int SRC, int DST>
__global__ __launch_bounds__(400, 2) void fused_ifft_crelu_fft_kernel()
{
    __shared__ float4 ZT[IMG][IMG + 1];
    __shared__ float2 Ds[IMG][IMG + 1];
    const int t = threadIdx.x;
    const size_t i0 = (size_t)blockIdx.x * 2;
    load_D_smem(Ds, t);
    const float2* in0 = getbuf<SRC>() + i0 * HW;
    const float2* in1 = in0 + HW;
    #pragma unroll
    for (int r = 0; r < 4; r++) {
        int idx = t + 400 * r;
        float2 v0 = in0[idx], v1 = in1[idx];
        ZT[idx / IMG][idx % IMG] = make_float4(v0.x, v0.y, v1.x, v1.y);
    }
    __syncthreads();

    const int k0 = t % 20, r0 = t / 20;
    float2 a[2][2][2];
    dft2d_pair<true>(ZT, Ds, k0, r0, a);   // inverse FFT

    __syncthreads();   // pass-2 reads done; safe to repack
    // CReLU + repack spatial values into ZT
    #pragma unroll
    for (int ri = 0; ri < 2; ri++)
        #pragma unroll
        for (int ci = 0; ci < 2; ci++) {
            float2 v0 = a[0][ri][ci], v1 = a[1][ri][ci];
            ZT[r0 + 20 * ri][k0 + 20 * ci] = make_float4(
                fmaxf(v0.x, 0.f), fmaxf(v0.y, 0.f),
                fmaxf(v1.x, 0.f), fmaxf(v1.y, 0.f));
        }
    __syncthreads();

    dft2d_pair<false>(ZT, Ds, k0, r0, a);  // forward FFT

    float2* o0 = getbuf<DST>() + i0 * HW;
    float2* o1 = o0 + HW;
    #pragma unroll
    for (int ri = 0; ri < 2; ri++)
        #pragma unroll
        for (int ci = 0; ci < 2; ci++) {
            int p = (r0 + 20 * ri) * IMG + (k0 + 20 * ci);
            o0[p] = a[0][ri][ci];
            o1[p] = a[1][ri][ci];
        }
}

// ---------------------------------------------------------------------------
// Last: inverse FFT (2 images/block), write real part to harness output.
// ---------------------------------------------------------------------------
template <int SRC>
__global__ __launch_bounds__(400, 2) void ifft_last_kernel(float* __restrict__ outp)
{
    __shared__ float4 ZT[IMG][IMG + 1];
    __shared__ float2 Ds[IMG][IMG + 1];
    const int t = threadIdx.x;
    const size_t i0 = (size_t)blockIdx.x * 2;
    load_D_smem(Ds, t);
    const float2* in0 = getbuf<SRC>() + i0 * HW;
    const float2* in1 = in0 + HW;
    #pragma unroll
    for (int r = 0; r < 4; r++) {
        int idx = t + 400 * r;
        float2 v0 = in0[idx], v1 = in1[idx];
        ZT[idx / IMG][idx % IMG] = make_float4(v0.x, v0.y, v1.x, v1.y);
    }
    __syncthreads();
    const int k0 = t % 20, r0 = t / 20;
    float2 a[2][2][2];
    dft2d_pair<true>(ZT, Ds, k0, r0, a);
    float* o0 = outp + i0 * HW;
    float* o1 = o0 + HW;
    #pragma unroll
    for (int ri = 0; ri < 2; ri++)
        #pragma unroll
        for (int ci = 0; ci < 2; ci++) {
            int p = (r0 + 20 * ri) * IMG + (k0 + 20 * ci);
            o0[p] = a[0][ri][ci].x;
            o1[p] = a[1][ri][ci].x;
        }
}

// ---------------------------------------------------------------------------
// mix40: O[b,o,hw] = sum_i F[b,i,hw] * W[i,o,hw], hw on lanes (coalesced).
// Block: hw-tile 32 (blockIdx.x), b-tile 16 (blockIdx.y). 640 thr = 20 warps;
// warp w: b-quad = w%4 (4 b's), o-oct = w/4 (8 o's). Register tile 4b x 8o.
// F/W staged through smem in i-chunks of 2 (28.5 KB).
// ---------------------------------------------------------------------------
template <int SRC, int DST>
__global__ __launch_bounds__(640, 1) void mix40_kernel(const float2* __restrict__ W)
{
    __shared__ float2 Fs[16][2][32];   // [b][i][hw]  8 KB
    __shared__ float2 Ws[2][40][32];   // [i][o][hw]  20.5 KB

    const float2* F = getbuf<SRC>();
    float2* O = getbuf<DST>();

    const int tid  = threadIdx.x;
    const int lane = tid & 31;
    const int warp = tid >> 5;
    const int bq   = (warp & 3) * 4;   // base b within tile
    const int oq   = (warp >> 2) * 8;  // base o
    const int hw0  = blockIdx.x * 32;
    const int b0   = blockIdx.y * 16;

    float2 acc[4][8];
    #pragma unroll
    for (int b = 0; b < 4; b++)
        #pragma unroll
        for (int o = 0; o < 8; o++)
            acc[b][o] = make_float2(0.f, 0.f);

    for (int chunk = 0; chunk < 20; chunk++) {
        const int i0 = chunk * 2;
        // stage F: 16b x 2i x 32hw = 1024 entries, coalesced 256B rows
        #pragma unroll
        for (int rep = 0; rep < 2; rep++) {
            int idx = tid + rep * 640;
            if (idx < 1024) {
                int b = idx >> 6, rem = idx & 63;
                int ii = rem >> 5, hw = rem & 31;
                Fs[b][ii][hw] = F[((size_t)(b0 + b) * CH + i0 + ii) * HW + hw0 + hw];
            }
        }
        // stage W: 2i x 40o x 32hw = 2560 entries
        #pragma unroll
        for (int rep = 0; rep < 4; rep++) {
            int idx = tid + rep * 640;
            int ii = idx / 1280, rem = idx % 1280;
            int o = rem >> 5, hw = rem & 31;
            Ws[ii][o][hw] = W[((size_t)(i0 + ii) * CH + o) * HW + hw0 + hw];
        }
        __syncthreads();
        #pragma unroll
        for (int ii = 0; ii < 2; ii++) {
            float2 f[4], wv[8];
            #pragma unroll
            for (int b = 0; b < 4; b++) f[b] = Fs[bq + b][ii][lane];
            #pragma unroll
            for (int o = 0; o < 8; o++) wv[o] = Ws[ii][oq + o][lane];
            #pragma unroll
            for (int b = 0; b < 4; b++)
                #pragma unroll
                for (int o = 0; o < 8; o++)
                    cmac(acc[b][o], f[b], wv[o]);
        }
        __syncthreads();
    }

    #pragma unroll
    for (int b = 0; b < 4; b++)
        #pragma unroll
        for (int o = 0; o < 8; o++)
            O[((size_t)(b0 + bq + b) * CH + oq + o) * HW + hw0 + lane] = acc[b][o];
}

// Layer-1 mix (inC=1): O[b,o,hw] = F[b,hw] * W1[o,hw]. Fully coalesced.
template <int SRC, int DST>
__global__ __launch_bounds__(400) void mix1_kernel(const float2* __restrict__ W)
{
    const float2* F = getbuf<SRC>();
    float2* O = getbuf<DST>();
    const int o = blockIdx.x;   // 0..39
    const int b = blockIdx.y;   // 0..255
    #pragma unroll
    for (int r = 0; r < 4; r++) {
        int hw = threadIdx.x + 400 * r;
        float2 acc = {0, 0};
        cmac(acc, F[(size_t)b * HW + hw], W[(size_t)o * HW + hw]);
        O[((size_t)b * CH + o) * HW + hw] = acc;
    }
}

// Layer-6 mix (outC=1): O[b,hw] = sum_i F[b,i,hw] * W6[i,hw]. Coalesced.
template <int SRC, int DST>
__global__ __launch_bounds__(400) void mix6_kernel(const float2* __restrict__ W)
{
    const float2* F = getbuf<SRC>();
    float2* O = getbuf<DST>();
    const int b = blockIdx.x;
    #pragma unroll
    for (int r = 0; r < 4; r++) {
        int hw = threadIdx.x + 400 * r;
        float2 acc = {0, 0};
        #pragma unroll 8
        for (int i = 0; i < CH; i++) {
            cmac(acc, F[((size_t)b * CH + i) * HW + hw], W[(size_t)i * HW + hw]);
        }
        O[(size_t)b * HW + hw] = acc;
    }
}

extern "C" void kernel_launch(void* const* d_in, const int* in_sizes, int n_in,
                              void* d_out, int out_size)
{
    const float*  x  = (const float*)d_in[0];
    const float2* w1 = (const float2*)d_in[1];
    const float2* w2 = (const float2*)d_in[2];
    const float2* w3 = (const float2*)d_in[3];
    const float2* w4 = (const float2*)d_in[4];
    const float2* w5 = (const float2*)d_in[5];
    const float2* w6 = (const float2*)d_in[6];
    float* out = (float*)d_out;

    const int nPair = BATCH * CH / 2;          // 5120 fused blocks
    const dim3 mixGrid(HW / 32, BATCH / 16);   // (50, 16)
    const dim3 mix1Grid(CH, BATCH);

    init_D_kernel<<<4, 400>>>();

    // Layer 1 (inC=1 -> outC=40)
    fft_first_kernel<0><<<BATCH / 2, 400>>>(x);              // x -> A (freq)
    mix1_kernel<0, 1><<<mix1Grid, 400>>>(w1);                // A -> B
    fused_ifft_crelu_fft_kernel<1, 0><<<nPair, 400>>>();     // B -> A

    // Layer 2
    mix40_kernel<0, 1><<<mixGrid, 640>>>(w2);                // A -> B
    fused_ifft_crelu_fft_kernel<1, 0><<<nPair, 400>>>();     // B -> A

    // Layer 3
    mix40_kernel<0, 1><<<mixGrid, 640>>>(w3);
    fused_ifft_crelu_fft_kernel<1, 0><<<nPair, 400>>>();

    // Layer 4
    mix40_kernel<0, 1><<<mixGrid, 640>>>(w4);
    fused_ifft_crelu_fft_kernel<1, 0><<<nPair, 400>>>();

    // Layer 5
    mix40_kernel<0, 1><<<mixGrid, 640>>>(w5);
    fused_ifft_crelu_fft_kernel<1, 0><<<nPair, 400>>>();     // B -> A

    // Layer 6 (inC=40 -> outC=1), final output = real(ifft2)
    mix6_kernel<0, 1><<<BATCH, 400>>>(w6);                   // A -> B
    ifft_last_kernel<1><<<BATCH / 2, 400>>>(out);            // B -> out
}